// round 6
// baseline (speedup 1.0000x reference)
#include <cuda_runtime.h>
#include <cstdint>
#include <cstddef>

#define T_TOK 4096
#define HDIM  1024
#define IDIM  512
#define NEXP  16
#define MAXTILES 64

// scratch + worklist (static device globals — no allocations)
__device__ float g_mid[(size_t)T_TOK * IDIM];
__device__ int g_tile_e[MAXTILES];
__device__ int g_tile_r0[MAXTILES];
__device__ int g_tile_rows[MAXTILES];
__device__ int g_ntiles;

__global__ void build_wl(const int* __restrict__ cnt) {
    if (threadIdx.x == 0) {
        int n = 0, r0 = 0;
        for (int e = 0; e < NEXP; e++) {
            int c = cnt[e];
            for (int s = 0; s < c; s += 128) {
                g_tile_e[n] = e;
                g_tile_r0[n] = r0 + s;
                g_tile_rows[n] = (c - s) < 128 ? (c - s) : 128;
                n++;
            }
            r0 += c;
        }
        g_ntiles = n;
    }
}

// GEMM1 + SwiGLU: mid[t, i] = silu(x@Wg)[t,i] * (x@Wu)[t,i]
// CTA: 128 rows x 64 cols (of I), computing gate AND up blocks together.
__global__ void __launch_bounds__(256) gemm1(const float* __restrict__ x,
                                             const float* __restrict__ w) {
    int t = blockIdx.x;
    if (t >= g_ntiles) return;
    int e = g_tile_e[t], row0 = g_tile_r0[t], rows = g_tile_rows[t];
    int cb = blockIdx.y * 64;                       // column block within I
    const float* Bg = w + (size_t)e * HDIM * (2 * IDIM) + cb;
    const float* Bu = Bg + IDIM;

    __shared__ float As[16][132];    // transposed A tile: As[k][row]
    __shared__ float Bgs[16][68];
    __shared__ float Bus[16][68];

    int tid = threadIdx.x;
    int tr4 = (tid / 8) * 4;         // 4 rows per thread
    int tc  = (tid % 8) * 8;         // 8 cols per thread

    // A load mapping: 128 rows x 4 float4 = 512 float4, 2 consecutive per thread
    int a_r  = tid / 2;
    int a_k4 = (tid % 2) * 2;
    // B load mapping: 16 rows x 16 float4 = 256 float4, 1 per thread per matrix
    int b_r  = tid / 16;
    int b_c4 = (tid % 16) * 4;

    float ag[4][8] = {}, au[4][8] = {};

    for (int k0 = 0; k0 < HDIM; k0 += 16) {
        int gr = row0 + a_r; if (gr >= T_TOK) gr = T_TOK - 1;   // safe clamp
        const float4* ap = (const float4*)(x + (size_t)gr * HDIM + k0);
        float4 v0 = ap[a_k4], v1 = ap[a_k4 + 1];
        int kk = a_k4 * 4;
        As[kk + 0][a_r] = v0.x; As[kk + 1][a_r] = v0.y;
        As[kk + 2][a_r] = v0.z; As[kk + 3][a_r] = v0.w;
        As[kk + 4][a_r] = v1.x; As[kk + 5][a_r] = v1.y;
        As[kk + 6][a_r] = v1.z; As[kk + 7][a_r] = v1.w;

        size_t boff = (size_t)(k0 + b_r) * (2 * IDIM) + b_c4;
        *(float4*)&Bgs[b_r][b_c4] = *(const float4*)(Bg + boff);
        *(float4*)&Bus[b_r][b_c4] = *(const float4*)(Bu + boff);
        __syncthreads();

        #pragma unroll
        for (int k = 0; k < 16; k++) {
            float a[4];
            a[0] = As[k][tr4 + 0]; a[1] = As[k][tr4 + 1];
            a[2] = As[k][tr4 + 2]; a[3] = As[k][tr4 + 3];
            float bg[8], bu[8];
            *(float4*)&bg[0] = *(const float4*)&Bgs[k][tc];
            *(float4*)&bg[4] = *(const float4*)&Bgs[k][tc + 4];
            *(float4*)&bu[0] = *(const float4*)&Bus[k][tc];
            *(float4*)&bu[4] = *(const float4*)&Bus[k][tc + 4];
            #pragma unroll
            for (int r = 0; r < 4; r++)
                #pragma unroll
                for (int c = 0; c < 8; c++) {
                    ag[r][c] += a[r] * bg[c];
                    au[r][c] += a[r] * bu[c];
                }
        }
        __syncthreads();
    }

    #pragma unroll
    for (int r = 0; r < 4; r++) {
        int lr = tr4 + r;
        if (lr < rows) {
            float* mp = g_mid + (size_t)(row0 + lr) * IDIM + cb + tc;
            #pragma unroll
            for (int c = 0; c < 8; c++) {
                float g = ag[r][c], u = au[r][c];
                float s = g / (1.0f + expf(-g));     // silu
                mp[c] = s * u;
            }
        }
    }
}

// GEMM2: out = mid @ down[e],  CTA: 128 rows x 64 cols (of H), K = IDIM
__global__ void __launch_bounds__(256) gemm2(const float* __restrict__ dwn,
                                             float* __restrict__ out) {
    int t = blockIdx.x;
    if (t >= g_ntiles) return;
    int e = g_tile_e[t], row0 = g_tile_r0[t], rows = g_tile_rows[t];
    int cb = blockIdx.y * 64;                       // column block within H
    const float* B = dwn + (size_t)e * IDIM * HDIM + cb;

    __shared__ float As[16][132];
    __shared__ float Bs[16][68];

    int tid = threadIdx.x;
    int tr4 = (tid / 8) * 4;
    int tc  = (tid % 8) * 8;

    int a_r  = tid / 2;
    int a_k4 = (tid % 2) * 2;
    int b_r  = tid / 16;
    int b_c4 = (tid % 16) * 4;

    float acc[4][8] = {};

    for (int k0 = 0; k0 < IDIM; k0 += 16) {
        int gr = row0 + a_r; if (gr >= T_TOK) gr = T_TOK - 1;
        const float4* ap = (const float4*)(g_mid + (size_t)gr * IDIM + k0);
        float4 v0 = ap[a_k4], v1 = ap[a_k4 + 1];
        int kk = a_k4 * 4;
        As[kk + 0][a_r] = v0.x; As[kk + 1][a_r] = v0.y;
        As[kk + 2][a_r] = v0.z; As[kk + 3][a_r] = v0.w;
        As[kk + 4][a_r] = v1.x; As[kk + 5][a_r] = v1.y;
        As[kk + 6][a_r] = v1.z; As[kk + 7][a_r] = v1.w;

        *(float4*)&Bs[b_r][b_c4] =
            *(const float4*)(B + (size_t)(k0 + b_r) * HDIM + b_c4);
        __syncthreads();

        #pragma unroll
        for (int k = 0; k < 16; k++) {
            float a[4];
            a[0] = As[k][tr4 + 0]; a[1] = As[k][tr4 + 1];
            a[2] = As[k][tr4 + 2]; a[3] = As[k][tr4 + 3];
            float b[8];
            *(float4*)&b[0] = *(const float4*)&Bs[k][tc];
            *(float4*)&b[4] = *(const float4*)&Bs[k][tc + 4];
            #pragma unroll
            for (int r = 0; r < 4; r++)
                #pragma unroll
                for (int c = 0; c < 8; c++)
                    acc[r][c] += a[r] * b[c];
        }
        __syncthreads();
    }

    #pragma unroll
    for (int r = 0; r < 4; r++) {
        int lr = tr4 + r;
        if (lr < rows) {
            float* op = out + (size_t)(row0 + lr) * HDIM + cb + tc;
            #pragma unroll
            for (int c = 0; c < 8; c++) op[c] = acc[r][c];
        }
    }
}

extern "C" void kernel_launch(void* const* d_in, const int* in_sizes, int n_in,
                              void* d_out, int out_size) {
    const float* x   = (const float*)d_in[0];
    const float* wgu = (const float*)d_in[1];
    const float* wd  = (const float*)d_in[2];
    const int*   cnt = (const int*)d_in[3];
    float* out = (float*)d_out;

    build_wl<<<1, 32>>>(cnt);
    gemm1<<<dim3(MAXTILES, IDIM / 64), 256>>>(x, wgu);
    gemm2<<<dim3(MAXTILES, HDIM / 64), 256>>>(wd, out);
}

// round 9
// speedup vs baseline: 3.5852x; 3.5852x over previous
#include <cuda_runtime.h>
#include <cuda_bf16.h>
#include <cstdint>
#include <cstddef>

#define T_TOK 4096
#define HDIM  1024
#define IDIM  512
#define NEXP  16
#define MAXTILES 64

// stage layout: A/B tiles 128 rows x 32 k bf16, row stride 80 B (conflict-free ldmatrix)
#define OFF_AL 10240
#define OFF_BH 20480
#define OFF_BL 30720
#define STAGE  40960
#define SMEMSZ (2 * STAGE)

// persistent scratch (static device globals — no allocations)
__device__ __align__(256) __nv_bfloat16 g_xh[T_TOK*HDIM], g_xl[T_TOK*HDIM];
__device__ __align__(256) __nv_bfloat16 g_wgh[NEXP*2*IDIM*HDIM], g_wgl[NEXP*2*IDIM*HDIM]; // [e][n<2I][h] K-major
__device__ __align__(256) __nv_bfloat16 g_wdh[NEXP*HDIM*IDIM],  g_wdl[NEXP*HDIM*IDIM];   // [e][h][i]  K-major
__device__ __align__(256) __nv_bfloat16 g_mh[T_TOK*IDIM], g_ml[T_TOK*IDIM];
__device__ int g_te[MAXTILES], g_tr0[MAXTILES], g_trows[MAXTILES], g_nt;

__device__ __forceinline__ uint32_t smem_u32(const void* p) {
    uint32_t a;
    asm("{ .reg .u64 t; cvta.to.shared.u64 t, %1; cvt.u32.u64 %0, t; }" : "=r"(a) : "l"(p));
    return a;
}
__device__ __forceinline__ void cp16(uint32_t s, const void* g) {
    asm volatile("cp.async.cg.shared.global [%0], [%1], 16;" :: "r"(s), "l"(g) : "memory");
}
__device__ __forceinline__ void ldsm4(uint32_t* r, uint32_t a) {
    asm volatile("ldmatrix.sync.aligned.m8n8.x4.shared.b16 {%0,%1,%2,%3}, [%4];"
                 : "=r"(r[0]), "=r"(r[1]), "=r"(r[2]), "=r"(r[3]) : "r"(a));
}
__device__ __forceinline__ void mma16816(float* c, const uint32_t* a, const uint32_t* b) {
    asm volatile(
        "mma.sync.aligned.m16n8k16.row.col.f32.bf16.bf16.f32 "
        "{%0,%1,%2,%3}, {%4,%5,%6,%7}, {%8,%9}, {%0,%1,%2,%3};"
        : "+f"(c[0]), "+f"(c[1]), "+f"(c[2]), "+f"(c[3])
        : "r"(a[0]), "r"(a[1]), "r"(a[2]), "r"(a[3]), "r"(b[0]), "r"(b[1]));
}
__device__ __forceinline__ void split(float v, __nv_bfloat16& h, __nv_bfloat16& l) {
    h = __float2bfloat16_rn(v);
    l = __float2bfloat16_rn(v - __bfloat162float(h));
}

__global__ void build_wl(const int* __restrict__ cnt) {
    if (threadIdx.x == 0) {
        int n = 0, r0 = 0;
        for (int e = 0; e < NEXP; e++) {
            int c = cnt[e];
            for (int s = 0; s < c; s += 128) {
                g_te[n] = e; g_tr0[n] = r0 + s;
                g_trows[n] = (c - s) < 128 ? (c - s) : 128; n++;
            }
            r0 += c;
        }
        g_nt = n;
    }
}

__global__ void prep_x(const float* __restrict__ x) {
    size_t i = (size_t)blockIdx.x * 256 + threadIdx.x;      // float4 index
    float4 v = ((const float4*)x)[i];
    __nv_bfloat16 h[4], l[4];
    split(v.x, h[0], l[0]); split(v.y, h[1], l[1]);
    split(v.z, h[2], l[2]); split(v.w, h[3], l[3]);
    __nv_bfloat162 p0, p1, q0, q1;
    p0.x = h[0]; p0.y = h[1]; p1.x = h[2]; p1.y = h[3];
    q0.x = l[0]; q0.y = l[1]; q1.x = l[2]; q1.y = l[3];
    ((__nv_bfloat162*)g_xh)[2*i] = p0; ((__nv_bfloat162*)g_xh)[2*i+1] = p1;
    ((__nv_bfloat162*)g_xl)[2*i] = q0; ((__nv_bfloat162*)g_xl)[2*i+1] = q1;
}

// transpose per-expert [RD][CD] f32 -> [CD][RD] bf16 hi/lo (K-major weights)
template<int RD, int CD, int W>
__global__ void prep_tr(const float* __restrict__ in) {
    __shared__ float t[32][33];
    int e = blockIdx.z;
    const float* I = in + (size_t)e * RD * CD;
    __nv_bfloat16* OH = (W ? g_wdh : g_wgh) + (size_t)e * RD * CD;
    __nv_bfloat16* OL = (W ? g_wdl : g_wgl) + (size_t)e * RD * CD;
    int c0 = blockIdx.x * 32, r0 = blockIdx.y * 32;
    int tx = threadIdx.x, ty = threadIdx.y;
    #pragma unroll
    for (int j = 0; j < 32; j += 8)
        t[ty + j][tx] = I[(size_t)(r0 + ty + j) * CD + c0 + tx];
    __syncthreads();
    #pragma unroll
    for (int j = 0; j < 32; j += 8) {
        __nv_bfloat16 h, l; split(t[tx][ty + j], h, l);
        size_t o = (size_t)(c0 + ty + j) * RD + r0 + tx;
        OH[o] = h; OL[o] = l;
    }
}

// G=1: [x @ wgu] + SwiGLU -> mid (bf16 hi/lo).  G=2: [mid @ wd] -> out (f32).
// CTA tile 128(M) x 128(N), K staged 32 deep, double-buffered cp.async.
template<int G>
__global__ void __launch_bounds__(256) gemm(float* __restrict__ out) {
    extern __shared__ char sm[];
    int t = blockIdx.x;
    if (t >= g_nt) return;
    int e = g_te[t], row0 = g_tr0[t], rows = g_trows[t];
    int tid = threadIdx.x, wid = tid >> 5, lane = tid & 31;
    int wm = wid >> 2, wn = wid & 3;
    uint32_t sb = smem_u32(sm);

    const __nv_bfloat16 *Ah, *Al, *Bh, *Bl;
    int KTOT, cb;
    if (G == 1) {
        KTOT = HDIM; cb = blockIdx.y * 64;                  // I-block of 64 (gate+up pair)
        Ah = g_xh; Al = g_xl;
        Bh = g_wgh + (size_t)e * 2 * IDIM * HDIM;
        Bl = g_wgl + (size_t)e * 2 * IDIM * HDIM;
    } else {
        KTOT = IDIM; cb = blockIdx.y * 128;                 // H-block of 128
        Ah = g_mh; Al = g_ml;
        Bh = g_wdh + (size_t)e * HDIM * IDIM;
        Bl = g_wdl + (size_t)e * HDIM * IDIM;
    }
    const int NS = KTOT / 32;

    auto load_stage = [&](int buf, int k0) {
        uint32_t so = sb + (uint32_t)buf * STAGE;
        #pragma unroll
        for (int i = 0; i < 2; i++) {
            int idx = tid + i * 256;
            int r = idx >> 2, q = idx & 3;
            uint32_t sA = so + (uint32_t)(r * 80 + q * 16);
            int gr = row0 + r; if (gr >= T_TOK) gr = T_TOK - 1;
            size_t ga = (size_t)gr * KTOT + k0 + q * 8;
            cp16(sA, Ah + ga);
            cp16(sA + OFF_AL, Al + ga);
            int n;
            if (G == 1) {
                int sub = r & 31, f = sub >> 3;
                n = cb + (r >> 5) * 16 + (f & 1) * 8 + (sub & 7) + ((f >= 2) ? 512 : 0);
            } else n = cb + r;
            size_t gb = (size_t)n * KTOT + k0 + q * 8;
            cp16(sA + OFF_BH, Bh + gb);
            cp16(sA + OFF_BL, Bl + gb);
        }
    };

    float acc[4][4][4] = {};
    // ldmatrix per-lane base offsets (bytes)
    uint32_t aRowB = (uint32_t)((wm * 64 + (lane & 15)) * 80 + (lane >> 4) * 16);
    uint32_t bRowB = (uint32_t)((wn * 32 + (lane >> 4) * 8 + (lane & 7)) * 80 + ((lane >> 3) & 1) * 16);

    load_stage(0, 0);
    asm volatile("cp.async.commit_group;" ::: "memory");

    for (int s = 0; s < NS; s++) {
        if (s + 1 < NS) load_stage((s + 1) & 1, (s + 1) * 32);
        asm volatile("cp.async.commit_group;" ::: "memory");
        asm volatile("cp.async.wait_group 1;" ::: "memory");
        __syncthreads();
        uint32_t so = sb + (uint32_t)(s & 1) * STAGE;
        #pragma unroll
        for (int ks = 0; ks < 2; ks++) {
            uint32_t ah[4][4], al[4][4], bh[4][2], bl[4][2];
            #pragma unroll
            for (int fm = 0; fm < 4; fm++) {
                uint32_t a = so + aRowB + fm * 1280 + ks * 32;
                ldsm4(ah[fm], a);
                ldsm4(al[fm], a + OFF_AL);
            }
            #pragma unroll
            for (int p = 0; p < 2; p++) {
                uint32_t b = so + OFF_BH + bRowB + p * 1280 + ks * 32;
                uint32_t r4[4];
                ldsm4(r4, b);
                bh[2*p][0] = r4[0]; bh[2*p][1] = r4[1];
                bh[2*p+1][0] = r4[2]; bh[2*p+1][1] = r4[3];
                ldsm4(r4, b + (OFF_BL - OFF_BH));
                bl[2*p][0] = r4[0]; bl[2*p][1] = r4[1];
                bl[2*p+1][0] = r4[2]; bl[2*p+1][1] = r4[3];
            }
            #pragma unroll
            for (int fm = 0; fm < 4; fm++)
                #pragma unroll
                for (int fn = 0; fn < 4; fn++) {
                    mma16816(acc[fm][fn], ah[fm], bh[fn]);   // hi*hi
                    mma16816(acc[fm][fn], ah[fm], bl[fn]);   // hi*lo
                    mma16816(acc[fm][fn], al[fm], bh[fn]);   // lo*hi
                }
        }
        __syncthreads();
    }

    if (G == 1) {
        // frags fn={0,1}: gate cols wn*16+{0..15}; fn={2,3}: matching up cols -> fused SwiGLU
        #pragma unroll
        for (int fm = 0; fm < 4; fm++)
            #pragma unroll
            for (int half = 0; half < 2; half++) {
                int lr = wm * 64 + fm * 16 + (lane >> 2) + half * 8;
                if (lr < rows) {
                    size_t base = (size_t)(row0 + lr) * IDIM + cb + wn * 16 + (lane & 3) * 2;
                    #pragma unroll
                    for (int f = 0; f < 2; f++) {
                        float g0 = acc[fm][f][half*2],     g1 = acc[fm][f][half*2+1];
                        float u0 = acc[fm][f+2][half*2],   u1 = acc[fm][f+2][half*2+1];
                        float v0 = u0 * g0 / (1.f + __expf(-g0));
                        float v1 = u1 * g1 / (1.f + __expf(-g1));
                        __nv_bfloat16 h0, l0, h1, l1;
                        split(v0, h0, l0); split(v1, h1, l1);
                        __nv_bfloat162 hv, lv;
                        hv.x = h0; hv.y = h1; lv.x = l0; lv.y = l1;
                        *(__nv_bfloat162*)(g_mh + base + f * 8) = hv;
                        *(__nv_bfloat162*)(g_ml + base + f * 8) = lv;
                    }
                }
            }
    } else {
        #pragma unroll
        for (int fm = 0; fm < 4; fm++)
            #pragma unroll
            for (int half = 0; half < 2; half++) {
                int lr = wm * 64 + fm * 16 + (lane >> 2) + half * 8;
                if (lr < rows) {
                    float* op = out + (size_t)(row0 + lr) * HDIM + cb + wn * 32 + (lane & 3) * 2;
                    #pragma unroll
                    for (int fn = 0; fn < 4; fn++) {
                        float2 v;
                        v.x = acc[fm][fn][half*2];
                        v.y = acc[fm][fn][half*2+1];
                        *(float2*)(op + fn * 8) = v;
                    }
                }
            }
    }
}

extern "C" void kernel_launch(void* const* d_in, const int* in_sizes, int n_in,
                              void* d_out, int out_size) {
    const float* x   = (const float*)d_in[0];
    const float* wgu = (const float*)d_in[1];
    const float* wd  = (const float*)d_in[2];
    const int*   cnt = (const int*)d_in[3];
    float* out = (float*)d_out;

    cudaFuncSetAttribute(gemm<1>, cudaFuncAttributeMaxDynamicSharedMemorySize, SMEMSZ);
    cudaFuncSetAttribute(gemm<2>, cudaFuncAttributeMaxDynamicSharedMemorySize, SMEMSZ);

    build_wl<<<1, 32>>>(cnt);
    prep_x<<<T_TOK * HDIM / 4 / 256, 256>>>(x);
    prep_tr<HDIM, 2 * IDIM, 0><<<dim3(2 * IDIM / 32, HDIM / 32, NEXP), dim3(32, 8)>>>(wgu);
    prep_tr<IDIM, HDIM, 1><<<dim3(HDIM / 32, IDIM / 32, NEXP), dim3(32, 8)>>>(wd);
    gemm<1><<<dim3(MAXTILES, IDIM / 64), 256, SMEMSZ>>>(out);
    gemm<2><<<dim3(MAXTILES, HDIM / 128), 256, SMEMSZ>>>(out);
}

// round 14
// speedup vs baseline: 4.2701x; 1.1910x over previous
#include <cuda_runtime.h>
#include <cuda_bf16.h>
#include <cstdint>
#include <cstddef>

#define T_TOK 4096
#define HDIM  1024
#define IDIM  512
#define NEXP  16
#define MAXTILES 64

// stage image: [Ah|Al|Bh|Bl], each quadrant 128 rows x 32 k bf16, 80 B row stride
#define QUAD   10240
#define OFF_AL 10240
#define OFF_BH 20480
#define OFF_BL 30720
#define STAGE  40960
#define BLK    20480            // one packed hi|lo pair (A or B) per stage
#define SMEMSZ (2 * STAGE + 16)

// packed tile images (static device globals — no allocations)
__device__ __align__(256) unsigned char g_xp[(size_t)MAXTILES * 32 * BLK];      // x:  [tile][stage][hi|lo]
__device__ __align__(256) unsigned char g_wg[(size_t)NEXP * 8 * 32 * BLK];      // wgu:[e][by][stage][hi|lo]
__device__ __align__(256) unsigned char g_wd[(size_t)NEXP * 8 * 16 * BLK];      // wd: [e][by][stage][hi|lo]
__device__ __align__(256) unsigned char g_m2[(size_t)MAXTILES * 16 * BLK];      // mid:[tile][stage][hi|lo]
__device__ int g_te[MAXTILES], g_tr0[MAXTILES], g_trows[MAXTILES], g_nt;

__device__ __forceinline__ uint32_t smem_u32(const void* p) {
    uint32_t a;
    asm("{ .reg .u64 t; cvta.to.shared.u64 t, %1; cvt.u32.u64 %0, t; }" : "=r"(a) : "l"(p));
    return a;
}
__device__ __forceinline__ void bulkcp(uint32_t dst, const void* src, uint32_t bytes, uint32_t mb) {
    asm volatile("cp.async.bulk.shared::cluster.global.mbarrier::complete_tx::bytes [%0], [%1], %2, [%3];"
                 :: "r"(dst), "l"(src), "r"(bytes), "r"(mb) : "memory");
}
__device__ __forceinline__ void mbar_init(uint32_t a, uint32_t c) {
    asm volatile("mbarrier.init.shared.b64 [%0], %1;" :: "r"(a), "r"(c) : "memory");
}
__device__ __forceinline__ void mbar_expect(uint32_t a, uint32_t bytes) {
    asm volatile("mbarrier.arrive.expect_tx.shared.b64 _, [%0], %1;" :: "r"(a), "r"(bytes) : "memory");
}
__device__ __forceinline__ void mbar_wait(uint32_t a, uint32_t ph) {
    asm volatile(
        "{\n\t.reg .pred P1;\n\t"
        "W%=:\n\t"
        "mbarrier.try_wait.parity.acquire.cta.shared::cta.b64 P1, [%0], %1, 0x989680;\n\t"
        "@P1 bra.uni D%=;\n\t"
        "bra.uni W%=;\n\t"
        "D%=:\n\t}" :: "r"(a), "r"(ph) : "memory");
}
__device__ __forceinline__ void ldsm4(uint32_t* r, uint32_t a) {
    asm volatile("ldmatrix.sync.aligned.m8n8.x4.shared.b16 {%0,%1,%2,%3}, [%4];"
                 : "=r"(r[0]), "=r"(r[1]), "=r"(r[2]), "=r"(r[3]) : "r"(a));
}
__device__ __forceinline__ void mma16816(float* c, const uint32_t* a, const uint32_t* b) {
    asm volatile(
        "mma.sync.aligned.m16n8k16.row.col.f32.bf16.bf16.f32 "
        "{%0,%1,%2,%3}, {%4,%5,%6,%7}, {%8,%9}, {%0,%1,%2,%3};"
        : "+f"(c[0]), "+f"(c[1]), "+f"(c[2]), "+f"(c[3])
        : "r"(a[0]), "r"(a[1]), "r"(a[2]), "r"(a[3]), "r"(b[0]), "r"(b[1]));
}
__device__ __forceinline__ void split(float v, __nv_bfloat16& h, __nv_bfloat16& l) {
    h = __float2bfloat16_rn(v);
    l = __float2bfloat16_rn(v - __bfloat162float(h));
}

__global__ void build_wl(const int* __restrict__ cnt) {
    if (threadIdx.x == 0) {
        int n = 0, r0 = 0;
        for (int e = 0; e < NEXP; e++) {
            int c = cnt[e];
            for (int s = 0; s < c; s += 128) {
                g_te[n] = e; g_tr0[n] = r0 + s;
                g_trows[n] = (c - s) < 128 ? (c - s) : 128; n++;
            }
            r0 += c;
        }
        g_nt = n;
    }
}

// pack x (f32) -> per-(tile,stage) smem-image blocks, bf16 hi|lo
__global__ void prep_xp(const float* __restrict__ x) {
    int t = blockIdx.x;
    if (t >= g_nt) return;
    int s = blockIdx.y, row0 = g_tr0[t];
    int tid = threadIdx.x, r = tid >> 1, half = tid & 1;
    int gr = row0 + r; if (gr >= T_TOK) gr = T_TOK - 1;
    const float4* src = (const float4*)(x + (size_t)gr * HDIM + s * 32 + half * 16);
    unsigned char* dst = g_xp + (size_t)(t * 32 + s) * BLK + r * 80 + half * 32;
    #pragma unroll
    for (int q = 0; q < 4; q++) {
        float4 f = src[q];
        __nv_bfloat16 h0, l0, h1, l1, h2, l2, h3, l3;
        split(f.x, h0, l0); split(f.y, h1, l1); split(f.z, h2, l2); split(f.w, h3, l3);
        __nv_bfloat162 ph0, ph1, pl0, pl1;
        ph0.x = h0; ph0.y = h1; ph1.x = h2; ph1.y = h3;
        pl0.x = l0; pl0.y = l1; pl1.x = l2; pl1.y = l3;
        uint2 vh, vl;
        vh.x = *(uint32_t*)&ph0; vh.y = *(uint32_t*)&ph1;
        vl.x = *(uint32_t*)&pl0; vl.y = *(uint32_t*)&pl1;
        *(uint2*)(dst + q * 8) = vh;
        *(uint2*)(dst + QUAD + q * 8) = vl;
    }
}

// pack weights (f32, n-contiguous) -> per-(e,by,stage) K-major smem-image blocks.
// W=0: gate_up [1024 k][1024 n] with gate/up interleave; W=1: down [512 k][1024 n] plain.
template<int RD, int CD, int W>
__global__ void prep_w(const float* __restrict__ in) {
    __shared__ float tb[32][33];
    int e = blockIdx.z;
    const float* I = in + (size_t)e * RD * CD;
    int c0 = blockIdx.x * 32, r0 = blockIdx.y * 32;
    int tx = threadIdx.x, ty = threadIdx.y;
    #pragma unroll
    for (int j = 0; j < 32; j += 8)
        tb[ty + j][tx] = I[(size_t)(r0 + ty + j) * CD + c0 + tx];
    __syncthreads();
    #pragma unroll
    for (int j = 0; j < 32; j += 8) {
        int col = c0 + ty + j, k = r0 + tx;
        __nv_bfloat16 h, l; split(tb[tx][ty + j], h, l);
        int by, r;
        if (W == 0) {
            int up = (col >= IDIM) ? 1 : 0;
            int o = up ? (col - IDIM) : col;
            by = o >> 6; int oo = o & 63;
            r = (oo >> 4) * 32 + up * 16 + ((oo >> 3) & 1) * 8 + (oo & 7);
        } else { by = col >> 7; r = col & 127; }
        int s = k >> 5, kin = k & 31;
        size_t blk = W ? (size_t)((e * 8 + by) * 16 + s) : (size_t)((e * 8 + by) * 32 + s);
        unsigned char* p = (W ? g_wd : g_wg) + blk * BLK + r * 80 + kin * 2;
        *(__nv_bfloat16*)p = h;
        *(__nv_bfloat16*)(p + QUAD) = l;
    }
}

// G=1: x@wgu + SwiGLU -> packed mid.  G=2: mid@wd -> out (f32).
// 128x128 CTA tile; 2-stage mbarrier pipeline fed by cp.async.bulk.
template<int G>
__global__ void __launch_bounds__(256, 2) gemm(float* __restrict__ out) {
    extern __shared__ char sm[];
    uint32_t sb = smem_u32(sm);
    int t = blockIdx.x;
    if (t >= g_nt) return;
    int e = g_te[t], row0 = g_tr0[t], rows = g_trows[t];
    int by = blockIdx.y;
    int tid = threadIdx.x, wid = tid >> 5, lane = tid & 31;
    int wm = wid >> 2, wn = wid & 3;
    const int NS = (G == 1) ? 32 : 16;

    const unsigned char* srcA = (G == 1) ? g_xp + (size_t)(t * 32) * BLK
                                         : g_m2 + (size_t)(t * 16) * BLK;
    const unsigned char* srcB = (G == 1) ? g_wg + (size_t)((e * 8 + by) * 32) * BLK
                                         : g_wd + (size_t)((e * 8 + by) * 16) * BLK;
    uint32_t mb = sb + 2 * STAGE;
    if (tid == 0) { mbar_init(mb, 1); mbar_init(mb + 8, 1); }
    __syncthreads();

    auto issue = [&](int s) {
        if (tid == 0) {
            uint32_t m = mb + (s & 1) * 8;
            uint32_t so = sb + (uint32_t)(s & 1) * STAGE;
            mbar_expect(m, STAGE);
            bulkcp(so,          srcA + (size_t)s * BLK, BLK, m);
            bulkcp(so + OFF_BH, srcB + (size_t)s * BLK, BLK, m);
        }
    };
    issue(0); issue(1);

    float acc[4][4][4] = {};
    uint32_t aRowB = (uint32_t)((wm * 64 + (lane & 15)) * 80 + (lane >> 4) * 16);
    uint32_t bRowB = (uint32_t)((wn * 32 + (lane >> 4) * 8 + (lane & 7)) * 80 + ((lane >> 3) & 1) * 16);

    for (int s = 0; s < NS; s++) {
        mbar_wait(mb + (s & 1) * 8, (s >> 1) & 1);
        uint32_t so = sb + (uint32_t)(s & 1) * STAGE;
        #pragma unroll
        for (int ks = 0; ks < 2; ks++) {
            uint32_t bh[4][2], bl[4][2];
            #pragma unroll
            for (int p = 0; p < 2; p++) {
                uint32_t b = so + OFF_BH + bRowB + p * 1280 + ks * 32;
                uint32_t r4[4];
                ldsm4(r4, b);
                bh[2*p][0] = r4[0]; bh[2*p][1] = r4[1];
                bh[2*p+1][0] = r4[2]; bh[2*p+1][1] = r4[3];
                ldsm4(r4, b + QUAD);
                bl[2*p][0] = r4[0]; bl[2*p][1] = r4[1];
                bl[2*p+1][0] = r4[2]; bl[2*p+1][1] = r4[3];
            }
            #pragma unroll
            for (int fm = 0; fm < 4; fm++) {
                uint32_t ah[4], al[4];
                uint32_t a = so + aRowB + fm * 1280 + ks * 32;
                ldsm4(ah, a);
                ldsm4(al, a + OFF_AL);
                #pragma unroll
                for (int fn = 0; fn < 4; fn++) {
                    mma16816(acc[fm][fn], ah, bh[fn]);   // hi*hi
                    mma16816(acc[fm][fn], ah, bl[fn]);   // hi*lo
                    mma16816(acc[fm][fn], al, bh[fn]);   // lo*hi
                }
            }
        }
        __syncthreads();
        if (s + 2 < NS) issue(s + 2);
    }

    if (G == 1) {
        // fn={0,1}: gate cols; fn={2,3}: matching up cols -> fused SwiGLU -> packed mid
        int s2 = by * 2 + (wn >> 1);
        #pragma unroll
        for (int fm = 0; fm < 4; fm++)
            #pragma unroll
            for (int half = 0; half < 2; half++) {
                int lr = wm * 64 + fm * 16 + (lane >> 2) + half * 8;
                if (lr < rows) {
                    #pragma unroll
                    for (int f = 0; f < 2; f++) {
                        float g0 = acc[fm][f][half*2],   g1 = acc[fm][f][half*2+1];
                        float u0 = acc[fm][f+2][half*2], u1 = acc[fm][f+2][half*2+1];
                        float v0 = u0 * g0 / (1.f + __expf(-g0));
                        float v1 = u1 * g1 / (1.f + __expf(-g1));
                        __nv_bfloat16 h0, l0, h1, l1;
                        split(v0, h0, l0); split(v1, h1, l1);
                        __nv_bfloat162 hv, lv;
                        hv.x = h0; hv.y = h1; lv.x = l0; lv.y = l1;
                        int kin = (wn & 1) * 16 + (lane & 3) * 2 + f * 8;
                        unsigned char* p = g_m2 + (size_t)(t * 16 + s2) * BLK + lr * 80 + kin * 2;
                        *(__nv_bfloat162*)p = hv;
                        *(__nv_bfloat162*)(p + QUAD) = lv;
                    }
                }
            }
    } else {
        int cb = by * 128;
        #pragma unroll
        for (int fm = 0; fm < 4; fm++)
            #pragma unroll
            for (int half = 0; half < 2; half++) {
                int lr = wm * 64 + fm * 16 + (lane >> 2) + half * 8;
                if (lr < rows) {
                    float* op = out + (size_t)(row0 + lr) * HDIM + cb + wn * 32 + (lane & 3) * 2;
                    #pragma unroll
                    for (int fn = 0; fn < 4; fn++) {
                        float2 v;
                        v.x = acc[fm][fn][half*2];
                        v.y = acc[fm][fn][half*2+1];
                        *(float2*)(op + fn * 8) = v;
                    }
                }
            }
    }
}

extern "C" void kernel_launch(void* const* d_in, const int* in_sizes, int n_in,
                              void* d_out, int out_size) {
    const float* x   = (const float*)d_in[0];
    const float* wgu = (const float*)d_in[1];
    const float* wd  = (const float*)d_in[2];
    const int*   cnt = (const int*)d_in[3];
    float* out = (float*)d_out;

    cudaFuncSetAttribute(gemm<1>, cudaFuncAttributeMaxDynamicSharedMemorySize, SMEMSZ);
    cudaFuncSetAttribute(gemm<2>, cudaFuncAttributeMaxDynamicSharedMemorySize, SMEMSZ);

    build_wl<<<1, 32>>>(cnt);
    prep_xp<<<dim3(MAXTILES, 32), 256>>>(x);
    prep_w<HDIM, 2 * IDIM, 0><<<dim3(32, HDIM / 32, NEXP), dim3(32, 8)>>>(wgu);
    prep_w<IDIM, HDIM, 1><<<dim3(32, IDIM / 32, NEXP), dim3(32, 8)>>>(wd);
    gemm<1><<<dim3(MAXTILES, 8), 256, SMEMSZ>>>(out);
    gemm<2><<<dim3(MAXTILES, 8), 256, SMEMSZ>>>(out);
}